// round 1
// baseline (speedup 1.0000x reference)
#include <cuda_runtime.h>
#include <cstdint>

// Problem constants (fixed shapes per reference)
#define NN   100000
#define EE   1600000
#define CINn 64
#define COUTn 128

// ---------------- scratch (static device globals; no runtime alloc) ----------------
__device__ float g_agg0[NN * CINn];          // 25.6 MB
__device__ float g_agg1[(size_t)NN * COUTn]; // 51.2 MB
__device__ float g_h0[(size_t)NN * COUTn];   // 51.2 MB
__device__ float g_y[(size_t)NN * COUTn];    // 51.2 MB
__device__ float g_h1[(size_t)NN * COUTn];   // 51.2 MB
__device__ float g_r[(size_t)NN * COUTn];    // 51.2 MB
__device__ float g_stats[4 * COUTn];         // sum0, sq0, sum1, sq1
__device__ float g_bnp[4 * COUTn];           // scale0, shift0, scale1, shift1

// ---------------- vector reduction (sm_90+): 4 floats per L2 atomic op ----------------
__device__ __forceinline__ void red_add_f4(float4* p, float4 v) {
    asm volatile("red.global.add.v4.f32 [%0], {%1,%2,%3,%4};"
                 :: "l"(p), "f"(v.x), "f"(v.y), "f"(v.z), "f"(v.w)
                 : "memory");
}

// ---------------- edge scatter: agg[dst] += feat[src]  ----------------
// C4 = float4s per node row (16 for 64 feats, 32 for 128 feats)
template <int C4>
__global__ void scatter_kernel(const int* __restrict__ src, const int* __restrict__ dst,
                               const float4* __restrict__ feat, float4* __restrict__ agg,
                               int E) {
    const long long tid = (long long)blockIdx.x * blockDim.x + threadIdx.x;
    constexpr int SH = (C4 == 16) ? 4 : 5;
    const int e = (int)(tid >> SH);
    if (e >= E) return;
    const int c = (int)(tid & (C4 - 1));
    const int s = __ldg(src + e);
    const int d = __ldg(dst + e);
    float4 v = feat[(long long)s * C4 + c];
    red_add_f4(agg + (long long)d * C4 + c, v);
}

// ---------------- tiled fp32 GEMM: C[n,0:128] = A@W1^T (+ B@W2^T) + bias ----------------
// W layout is [128, K] row-major (as given). BM=64 rows, BN=128 cols, BK=16.
// Optionally accumulates per-column sum / sum-of-squares into stats[0:128]/stats[128:256].
__global__ __launch_bounds__(256) void gemm_kernel(
    const float* __restrict__ A, const float* __restrict__ W1,
    const float* __restrict__ B, const float* __restrict__ W2,
    const float* __restrict__ bias, float* __restrict__ C,
    float* __restrict__ stats, int Nn, int K) {

    __shared__ float As[16][72];    // padded to dodge store conflicts
    __shared__ float Ws[16][128];
    __shared__ float sh_sum[128];
    __shared__ float sh_sq[128];

    const int tid  = threadIdx.x;
    const int row0 = blockIdx.x * 64;
    const int warp = tid >> 5;
    const int lane = tid & 31;
    const int tm   = warp * 8;   // 8 rows per thread
    const int tn   = lane * 4;   // 4 cols per thread

    float acc[8][4];
#pragma unroll
    for (int i = 0; i < 8; i++)
#pragma unroll
        for (int j = 0; j < 4; j++) acc[i][j] = 0.f;

    const int nmat = (B != nullptr) ? 2 : 1;
    for (int mat = 0; mat < nmat; mat++) {
        const float* Ap = mat ? B : A;
        const float* Wp = mat ? W2 : W1;
        for (int k0 = 0; k0 < K; k0 += 16) {
            // load A tile: 64 rows x 16 k (one float4 per thread)
            {
                const int m  = tid >> 2;
                const int kq = (tid & 3) * 4;
                const int r  = row0 + m;
                float4 v = make_float4(0.f, 0.f, 0.f, 0.f);
                if (r < Nn) v = *(const float4*)(Ap + (long long)r * K + k0 + kq);
                As[kq + 0][m] = v.x; As[kq + 1][m] = v.y;
                As[kq + 2][m] = v.z; As[kq + 3][m] = v.w;
            }
            // load W tile: 128 n x 16 k -> Ws[k][n] (two float4 per thread)
            {
                const int n  = tid >> 1;
                const int kq = (tid & 1) * 8;
                const float* wrow = Wp + (long long)n * K + k0 + kq;
                float4 v0 = *(const float4*)(wrow);
                float4 v1 = *(const float4*)(wrow + 4);
                Ws[kq + 0][n] = v0.x; Ws[kq + 1][n] = v0.y;
                Ws[kq + 2][n] = v0.z; Ws[kq + 3][n] = v0.w;
                Ws[kq + 4][n] = v1.x; Ws[kq + 5][n] = v1.y;
                Ws[kq + 6][n] = v1.z; Ws[kq + 7][n] = v1.w;
            }
            __syncthreads();
#pragma unroll
            for (int kk = 0; kk < 16; kk++) {
                const float4 a0 = *(const float4*)&As[kk][tm];
                const float4 a1 = *(const float4*)&As[kk][tm + 4];
                const float4 w  = *(const float4*)&Ws[kk][tn];
                const float a[8] = {a0.x, a0.y, a0.z, a0.w, a1.x, a1.y, a1.z, a1.w};
#pragma unroll
                for (int i = 0; i < 8; i++) {
                    acc[i][0] = fmaf(a[i], w.x, acc[i][0]);
                    acc[i][1] = fmaf(a[i], w.y, acc[i][1]);
                    acc[i][2] = fmaf(a[i], w.z, acc[i][2]);
                    acc[i][3] = fmaf(a[i], w.w, acc[i][3]);
                }
            }
            __syncthreads();
        }
    }

    // bias, store, per-block BN stats
    const float bb0 = bias[tn], bb1 = bias[tn + 1], bb2 = bias[tn + 2], bb3 = bias[tn + 3];
    float psum[4] = {0.f, 0.f, 0.f, 0.f};
    float psq[4]  = {0.f, 0.f, 0.f, 0.f};
#pragma unroll
    for (int i = 0; i < 8; i++) {
        const int r = row0 + tm + i;
        if (r < Nn) {
            float4 o;
            o.x = acc[i][0] + bb0; o.y = acc[i][1] + bb1;
            o.z = acc[i][2] + bb2; o.w = acc[i][3] + bb3;
            *(float4*)(C + (long long)r * 128 + tn) = o;
            psum[0] += o.x; psum[1] += o.y; psum[2] += o.z; psum[3] += o.w;
            psq[0] += o.x * o.x; psq[1] += o.y * o.y;
            psq[2] += o.z * o.z; psq[3] += o.w * o.w;
        }
    }
    if (stats) {
        if (tid < 128) { sh_sum[tid] = 0.f; sh_sq[tid] = 0.f; }
        __syncthreads();
#pragma unroll
        for (int j = 0; j < 4; j++) {
            atomicAdd(&sh_sum[tn + j], psum[j]);
            atomicAdd(&sh_sq[tn + j], psq[j]);
        }
        __syncthreads();
        if (tid < 128) {
            atomicAdd(&stats[tid], sh_sum[tid]);
            atomicAdd(&stats[128 + tid], sh_sq[tid]);
        }
    }
}

// ---------------- BN finalize: scale/shift from accumulated stats ----------------
__global__ void finalize_kernel(const float* __restrict__ stats,
                                const float* __restrict__ gamma,
                                const float* __restrict__ beta,
                                float* __restrict__ bnp, float invN) {
    const int c = threadIdx.x;  // 128 threads
    const float mu   = stats[c] * invN;
    const float var  = stats[128 + c] * invN - mu * mu;
    const float rstd = rsqrtf(var + 1e-5f);
    const float sc   = rstd * gamma[c];
    bnp[c]       = sc;
    bnp[128 + c] = beta[c] - mu * sc;
}

// ---------------- y = relu(h*scale + shift) ----------------
__global__ void bnrelu_kernel(const float4* __restrict__ h, const float* __restrict__ bnp,
                              float4* __restrict__ y, int total4) {
    const int i = blockIdx.x * blockDim.x + threadIdx.x;
    if (i >= total4) return;
    const int c = (i & 31) * 4;  // row = 32 float4s (128 cols)
    const float4 v = h[i];
    float4 o;
    o.x = fmaxf(fmaf(v.x, bnp[c + 0], bnp[128 + c + 0]), 0.f);
    o.y = fmaxf(fmaf(v.y, bnp[c + 1], bnp[128 + c + 1]), 0.f);
    o.z = fmaxf(fmaf(v.z, bnp[c + 2], bnp[128 + c + 2]), 0.f);
    o.w = fmaxf(fmaf(v.w, bnp[c + 3], bnp[128 + c + 3]), 0.f);
    y[i] = o;
}

// ---------------- out = relu(h1*scale + shift + r) ----------------
__global__ void final_kernel(const float4* __restrict__ h1, const float* __restrict__ bnp,
                             const float4* __restrict__ r, float4* __restrict__ out,
                             int total4) {
    const int i = blockIdx.x * blockDim.x + threadIdx.x;
    if (i >= total4) return;
    const int c = (i & 31) * 4;
    const float4 v = h1[i];
    const float4 rv = r[i];
    float4 o;
    o.x = fmaxf(fmaf(v.x, bnp[c + 0], bnp[128 + c + 0]) + rv.x, 0.f);
    o.y = fmaxf(fmaf(v.y, bnp[c + 1], bnp[128 + c + 1]) + rv.y, 0.f);
    o.z = fmaxf(fmaf(v.z, bnp[c + 2], bnp[128 + c + 2]) + rv.z, 0.f);
    o.w = fmaxf(fmaf(v.w, bnp[c + 3], bnp[128 + c + 3]) + rv.w, 0.f);
    out[i] = o;
}

// ---------------- launch ----------------
extern "C" void kernel_launch(void* const* d_in, const int* in_sizes, int n_in,
                              void* d_out, int out_size) {
    const float* x    = (const float*)d_in[0];
    const int*   ei   = (const int*)d_in[1];
    const float* Wr0  = (const float*)d_in[2];
    const float* Wn0  = (const float*)d_in[3];
    const float* b0   = (const float*)d_in[4];
    const float* g0   = (const float*)d_in[5];
    const float* be0  = (const float*)d_in[6];
    const float* Wr1  = (const float*)d_in[7];
    const float* Wn1  = (const float*)d_in[8];
    const float* b1   = (const float*)d_in[9];
    const float* g1   = (const float*)d_in[10];
    const float* be1  = (const float*)d_in[11];
    const float* Wlin = (const float*)d_in[12];
    const float* blin = (const float*)d_in[13];
    float* out = (float*)d_out;

    const int N = in_sizes[0] / CINn;
    const int E = in_sizes[1] / 2;
    const int* src = ei;
    const int* dst = ei + E;

    float *agg0, *agg1, *h0, *y, *h1, *r, *stats, *bnp;
    cudaGetSymbolAddress((void**)&agg0,  g_agg0);
    cudaGetSymbolAddress((void**)&agg1,  g_agg1);
    cudaGetSymbolAddress((void**)&h0,    g_h0);
    cudaGetSymbolAddress((void**)&y,     g_y);
    cudaGetSymbolAddress((void**)&h1,    g_h1);
    cudaGetSymbolAddress((void**)&r,     g_r);
    cudaGetSymbolAddress((void**)&stats, g_stats);
    cudaGetSymbolAddress((void**)&bnp,   g_bnp);

    cudaMemsetAsync(agg0,  0, (size_t)N * CINn * sizeof(float));
    cudaMemsetAsync(agg1,  0, (size_t)N * COUTn * sizeof(float));
    cudaMemsetAsync(stats, 0, 4 * COUTn * sizeof(float));

    const int gemmBlocks = (N + 63) / 64;

    // Layer 0 aggregation: agg0[dst] += x[src]
    {
        const long long T = (long long)E * 16;
        const int th = 256;
        const int bl = (int)((T + th - 1) / th);
        scatter_kernel<16><<<bl, th>>>(src, dst, (const float4*)x, (float4*)agg0, E);
    }
    // Residual projection: r = x @ Wlin^T + blin
    gemm_kernel<<<gemmBlocks, 256>>>(x, Wlin, nullptr, nullptr, blin, r, nullptr, N, CINn);
    // h0 = x @ Wr0^T + agg0 @ Wn0^T + b0 (+ BN stats)
    gemm_kernel<<<gemmBlocks, 256>>>(x, Wr0, agg0, Wn0, b0, h0, stats, N, CINn);
    finalize_kernel<<<1, 128>>>(stats, g0, be0, bnp, 1.0f / (float)N);
    // y = relu(bn(h0))
    {
        const int T4 = N * 32;
        bnrelu_kernel<<<(T4 + 255) / 256, 256>>>((const float4*)h0, bnp, (float4*)y, T4);
    }
    // Layer 1 aggregation: agg1[dst] += y[src]
    {
        const long long T = (long long)E * 32;
        const int th = 256;
        const int bl = (int)((T + th - 1) / th);
        scatter_kernel<32><<<bl, th>>>(src, dst, (const float4*)y, (float4*)agg1, E);
    }
    // h1 = y @ Wr1^T + agg1 @ Wn1^T + b1 (+ BN stats)
    gemm_kernel<<<gemmBlocks, 256>>>(y, Wr1, agg1, Wn1, b1, h1, stats + 2 * COUTn, N, COUTn);
    finalize_kernel<<<1, 128>>>(stats + 2 * COUTn, g1, be1, bnp + 2 * COUTn, 1.0f / (float)N);
    // out = relu(bn(h1) + r)
    {
        const int T4 = N * 32;
        final_kernel<<<(T4 + 255) / 256, 256>>>((const float4*)h1, bnp + 2 * COUTn,
                                                (const float4*)r, (float4*)out, T4);
    }
}

// round 2
// speedup vs baseline: 1.2207x; 1.2207x over previous
#include <cuda_runtime.h>
#include <cstdint>

typedef unsigned long long ull;

// Problem constants (fixed shapes per reference)
#define NN    100000
#define EE    1600000
#define CINn  64
#define COUTn 128
#define SCAN_B 512

// ---------------- scratch (static device globals; no runtime alloc) ----------------
__device__ float g_agg0[(size_t)NN * CINn];   // 25.6 MB
__device__ float g_agg1[(size_t)NN * COUTn];  // 51.2 MB
__device__ float g_h0[(size_t)NN * COUTn];
__device__ float g_y[(size_t)NN * COUTn];
__device__ float g_h1[(size_t)NN * COUTn];
__device__ float g_r[(size_t)NN * COUTn];
__device__ float g_stats[4 * COUTn];
__device__ float g_bnp[4 * COUTn];
// CSR scratch
__device__ int g_deg[NN];
__device__ int g_lscan[NN];
__device__ int g_part[256];
__device__ int g_rowptr[NN + 1];
__device__ int g_cursor[NN];
__device__ int g_eidx[EE];

// ---------------- packed fp32x2 FMA (sm_103a FFMA2 path) ----------------
#define FMA2(acc, a, w) \
    asm("fma.rn.f32x2 %0, %1, %2, %0;" : "+l"(acc) : "l"(a), "l"(w))

__device__ __forceinline__ ull dup2(float f) {
    ull r;
    asm("mov.b64 %0, {%1, %1};" : "=l"(r) : "f"(f));
    return r;
}

union F2 { ull u; float2 f; };

// =============================================================================
// CSR build: histogram -> scan -> fill
// =============================================================================
__global__ void hist_kernel(const int* __restrict__ dst, int* __restrict__ deg, int E) {
    const int e = blockIdx.x * blockDim.x + threadIdx.x;
    if (e < E) atomicAdd(&deg[dst[e]], 1);
}

__global__ void scan1_kernel(const int* __restrict__ deg, int* __restrict__ lscan,
                             int* __restrict__ part, int N) {
    __shared__ int sh[SCAN_B];
    const int i = blockIdx.x * SCAN_B + threadIdx.x;
    const int v = (i < N) ? deg[i] : 0;
    sh[threadIdx.x] = v;
    __syncthreads();
#pragma unroll
    for (int off = 1; off < SCAN_B; off <<= 1) {
        int t = (threadIdx.x >= off) ? sh[threadIdx.x - off] : 0;
        __syncthreads();
        sh[threadIdx.x] += t;
        __syncthreads();
    }
    if (i < N) lscan[i] = sh[threadIdx.x] - v;  // exclusive local scan
    if (threadIdx.x == SCAN_B - 1) part[blockIdx.x] = sh[threadIdx.x];
}

__global__ void scan2_kernel(int* __restrict__ part, int nb) {
    __shared__ int sh[256];
    const int v = (threadIdx.x < nb) ? part[threadIdx.x] : 0;
    sh[threadIdx.x] = v;
    __syncthreads();
#pragma unroll
    for (int off = 1; off < 256; off <<= 1) {
        int t = (threadIdx.x >= off) ? sh[threadIdx.x - off] : 0;
        __syncthreads();
        sh[threadIdx.x] += t;
        __syncthreads();
    }
    if (threadIdx.x < nb) part[threadIdx.x] = sh[threadIdx.x] - v;  // exclusive
}

__global__ void scan3_kernel(const int* __restrict__ lscan, const int* __restrict__ part,
                             int* __restrict__ rowptr, int* __restrict__ cursor,
                             int N, int E) {
    const int i = blockIdx.x * blockDim.x + threadIdx.x;
    if (i < N) {
        const int r = lscan[i] + part[i / SCAN_B];
        rowptr[i] = r;
        cursor[i] = r;
    }
    if (i == 0) rowptr[N] = E;
}

__global__ void fill_kernel(const int* __restrict__ src, const int* __restrict__ dst,
                            int* __restrict__ cursor, int* __restrict__ eidx, int E) {
    const int e = blockIdx.x * blockDim.x + threadIdx.x;
    if (e < E) {
        const int pos = atomicAdd(&cursor[dst[e]], 1);
        eidx[pos] = src[e];
    }
}

// =============================================================================
// Gather aggregation: agg[n] = sum over in-edges of feat[src]. No atomics.
// C4 = float4s per row (16 for 64 feats, 32 for 128 feats). One group per node.
// =============================================================================
template <int C4>
__global__ void gather_kernel(const int* __restrict__ rowptr, const int* __restrict__ eidx,
                              const float4* __restrict__ feat, float4* __restrict__ agg,
                              int N) {
    constexpr int NPB = 256 / C4;
    const int g = threadIdx.x / C4;
    const int c = threadIdx.x % C4;
    const int node = blockIdx.x * NPB + g;
    if (node >= N) return;
    const int beg = rowptr[node];
    const int end = rowptr[node + 1];
    float4 acc = make_float4(0.f, 0.f, 0.f, 0.f);
    int e = beg;
    for (; e + 1 < end; e += 2) {
        const int s0 = eidx[e];
        const int s1 = eidx[e + 1];
        const float4 v0 = feat[(size_t)s0 * C4 + c];
        const float4 v1 = feat[(size_t)s1 * C4 + c];
        acc.x += v0.x; acc.y += v0.y; acc.z += v0.z; acc.w += v0.w;
        acc.x += v1.x; acc.y += v1.y; acc.z += v1.z; acc.w += v1.w;
    }
    if (e < end) {
        const int s = eidx[e];
        const float4 v = feat[(size_t)s * C4 + c];
        acc.x += v.x; acc.y += v.y; acc.z += v.z; acc.w += v.w;
    }
    agg[(size_t)node * C4 + c] = acc;
}

// =============================================================================
// Tiled fp32x2 GEMM: C[n,0:128] = A@W1^T (+ B@W2^T) + bias, optional BN stats.
// BM=64, BN=128, BK=16. Inner loop uses packed fma.rn.f32x2 (2 MAC/lane/instr).
// As2 holds duplicated (a,a) pairs so no repacking happens in the mainloop;
// W pairs are a straight 64-bit reinterpret of adjacent smem floats.
// =============================================================================
__global__ __launch_bounds__(256) void gemm_kernel(
    const float* __restrict__ A, const float* __restrict__ W1,
    const float* __restrict__ B, const float* __restrict__ W2,
    const float* __restrict__ bias, float* __restrict__ C,
    float* __restrict__ stats, int Nn, int K) {

    __shared__ ull As2[16 * 65];   // [k][m] duplicated pairs, stride 65 (conflict dodge)
    __shared__ float Ws[16][128];
    __shared__ float sh_sum[128];
    __shared__ float sh_sq[128];

    const int tid  = threadIdx.x;
    const int row0 = blockIdx.x * 64;
    const int warp = tid >> 5;
    const int lane = tid & 31;
    const int tm   = warp * 8;   // 8 rows per thread
    const int tn   = lane * 4;   // 4 cols per thread

    ull acc2[8][2];
#pragma unroll
    for (int i = 0; i < 8; i++) { acc2[i][0] = 0ull; acc2[i][1] = 0ull; }

    const int nmat = (B != nullptr) ? 2 : 1;
    for (int mat = 0; mat < nmat; mat++) {
        const float* Ap = mat ? B : A;
        const float* Wp = mat ? W2 : W1;
        for (int k0 = 0; k0 < K; k0 += 16) {
            // A tile: 64 rows x 16 k, stored duplicated (a,a)
            {
                const int m  = tid >> 2;
                const int kq = (tid & 3) * 4;
                const int r  = row0 + m;
                float4 v = make_float4(0.f, 0.f, 0.f, 0.f);
                if (r < Nn) v = *(const float4*)(Ap + (size_t)r * K + k0 + kq);
                As2[(kq + 0) * 65 + m] = dup2(v.x);
                As2[(kq + 1) * 65 + m] = dup2(v.y);
                As2[(kq + 2) * 65 + m] = dup2(v.z);
                As2[(kq + 3) * 65 + m] = dup2(v.w);
            }
            // W tile: 128 n x 16 k -> Ws[k][n]
            {
                const int n  = tid >> 1;
                const int kq = (tid & 1) * 8;
                const float* wrow = Wp + (size_t)n * K + k0 + kq;
                float4 v0 = *(const float4*)(wrow);
                float4 v1 = *(const float4*)(wrow + 4);
                Ws[kq + 0][n] = v0.x; Ws[kq + 1][n] = v0.y;
                Ws[kq + 2][n] = v0.z; Ws[kq + 3][n] = v0.w;
                Ws[kq + 4][n] = v1.x; Ws[kq + 5][n] = v1.y;
                Ws[kq + 6][n] = v1.z; Ws[kq + 7][n] = v1.w;
            }
            __syncthreads();
#pragma unroll
            for (int kk = 0; kk < 16; kk++) {
                const ull* ar = &As2[kk * 65 + tm];           // broadcast reads
                const ull w01 = *(const ull*)&Ws[kk][tn];      // (w0,w1)
                const ull w23 = *(const ull*)&Ws[kk][tn + 2];  // (w2,w3)
#pragma unroll
                for (int i = 0; i < 8; i++) {
                    const ull a = ar[i];
                    FMA2(acc2[i][0], a, w01);
                    FMA2(acc2[i][1], a, w23);
                }
            }
            __syncthreads();
        }
    }

    // bias, store, per-block BN stats
    const float bb0 = bias[tn], bb1 = bias[tn + 1], bb2 = bias[tn + 2], bb3 = bias[tn + 3];
    float psum[4] = {0.f, 0.f, 0.f, 0.f};
    float psq[4]  = {0.f, 0.f, 0.f, 0.f};
#pragma unroll
    for (int i = 0; i < 8; i++) {
        const int r = row0 + tm + i;
        if (r < Nn) {
            F2 p0, p1;
            p0.u = acc2[i][0];
            p1.u = acc2[i][1];
            float4 o;
            o.x = p0.f.x + bb0; o.y = p0.f.y + bb1;
            o.z = p1.f.x + bb2; o.w = p1.f.y + bb3;
            *(float4*)(C + (size_t)r * 128 + tn) = o;
            psum[0] += o.x; psum[1] += o.y; psum[2] += o.z; psum[3] += o.w;
            psq[0] += o.x * o.x; psq[1] += o.y * o.y;
            psq[2] += o.z * o.z; psq[3] += o.w * o.w;
        }
    }
    if (stats) {
        if (tid < 128) { sh_sum[tid] = 0.f; sh_sq[tid] = 0.f; }
        __syncthreads();
#pragma unroll
        for (int j = 0; j < 4; j++) {
            atomicAdd(&sh_sum[tn + j], psum[j]);
            atomicAdd(&sh_sq[tn + j], psq[j]);
        }
        __syncthreads();
        if (tid < 128) {
            atomicAdd(&stats[tid], sh_sum[tid]);
            atomicAdd(&stats[128 + tid], sh_sq[tid]);
        }
    }
}

// ---------------- BN finalize ----------------
__global__ void finalize_kernel(const float* __restrict__ stats,
                                const float* __restrict__ gamma,
                                const float* __restrict__ beta,
                                float* __restrict__ bnp, float invN) {
    const int c = threadIdx.x;  // 128 threads
    const float mu   = stats[c] * invN;
    const float var  = stats[128 + c] * invN - mu * mu;
    const float rstd = rsqrtf(var + 1e-5f);
    const float sc   = rstd * gamma[c];
    bnp[c]       = sc;
    bnp[128 + c] = beta[c] - mu * sc;
}

// ---------------- y = relu(h*scale + shift) ----------------
__global__ void bnrelu_kernel(const float4* __restrict__ h, const float* __restrict__ bnp,
                              float4* __restrict__ y, int total4) {
    const int i = blockIdx.x * blockDim.x + threadIdx.x;
    if (i >= total4) return;
    const int c = (i & 31) * 4;
    const float4 v = h[i];
    float4 o;
    o.x = fmaxf(fmaf(v.x, bnp[c + 0], bnp[128 + c + 0]), 0.f);
    o.y = fmaxf(fmaf(v.y, bnp[c + 1], bnp[128 + c + 1]), 0.f);
    o.z = fmaxf(fmaf(v.z, bnp[c + 2], bnp[128 + c + 2]), 0.f);
    o.w = fmaxf(fmaf(v.w, bnp[c + 3], bnp[128 + c + 3]), 0.f);
    y[i] = o;
}

// ---------------- out = relu(h1*scale + shift + r) ----------------
__global__ void final_kernel(const float4* __restrict__ h1, const float* __restrict__ bnp,
                             const float4* __restrict__ r, float4* __restrict__ out,
                             int total4) {
    const int i = blockIdx.x * blockDim.x + threadIdx.x;
    if (i >= total4) return;
    const int c = (i & 31) * 4;
    const float4 v = h1[i];
    const float4 rv = r[i];
    float4 o;
    o.x = fmaxf(fmaf(v.x, bnp[c + 0], bnp[128 + c + 0]) + rv.x, 0.f);
    o.y = fmaxf(fmaf(v.y, bnp[c + 1], bnp[128 + c + 1]) + rv.y, 0.f);
    o.z = fmaxf(fmaf(v.z, bnp[c + 2], bnp[128 + c + 2]) + rv.z, 0.f);
    o.w = fmaxf(fmaf(v.w, bnp[c + 3], bnp[128 + c + 3]) + rv.w, 0.f);
    out[i] = o;
}

// ---------------- launch ----------------
extern "C" void kernel_launch(void* const* d_in, const int* in_sizes, int n_in,
                              void* d_out, int out_size) {
    const float* x    = (const float*)d_in[0];
    const int*   ei   = (const int*)d_in[1];
    const float* Wr0  = (const float*)d_in[2];
    const float* Wn0  = (const float*)d_in[3];
    const float* b0   = (const float*)d_in[4];
    const float* g0   = (const float*)d_in[5];
    const float* be0  = (const float*)d_in[6];
    const float* Wr1  = (const float*)d_in[7];
    const float* Wn1  = (const float*)d_in[8];
    const float* b1   = (const float*)d_in[9];
    const float* g1   = (const float*)d_in[10];
    const float* be1  = (const float*)d_in[11];
    const float* Wlin = (const float*)d_in[12];
    const float* blin = (const float*)d_in[13];
    float* out = (float*)d_out;

    const int N = in_sizes[0] / CINn;
    const int E = in_sizes[1] / 2;
    const int* src = ei;
    const int* dst = ei + E;

    float *agg0, *agg1, *h0, *y, *h1, *r, *stats, *bnp;
    int *deg, *lscan, *part, *rowptr, *cursor, *eidx;
    cudaGetSymbolAddress((void**)&agg0,   g_agg0);
    cudaGetSymbolAddress((void**)&agg1,   g_agg1);
    cudaGetSymbolAddress((void**)&h0,     g_h0);
    cudaGetSymbolAddress((void**)&y,      g_y);
    cudaGetSymbolAddress((void**)&h1,     g_h1);
    cudaGetSymbolAddress((void**)&r,      g_r);
    cudaGetSymbolAddress((void**)&stats,  g_stats);
    cudaGetSymbolAddress((void**)&bnp,    g_bnp);
    cudaGetSymbolAddress((void**)&deg,    g_deg);
    cudaGetSymbolAddress((void**)&lscan,  g_lscan);
    cudaGetSymbolAddress((void**)&part,   g_part);
    cudaGetSymbolAddress((void**)&rowptr, g_rowptr);
    cudaGetSymbolAddress((void**)&cursor, g_cursor);
    cudaGetSymbolAddress((void**)&eidx,   g_eidx);

    cudaMemsetAsync(deg,   0, (size_t)N * sizeof(int));
    cudaMemsetAsync(stats, 0, 4 * COUTn * sizeof(float));

    const int nb = (N + SCAN_B - 1) / SCAN_B;  // 196 for N=100000

    // ---- CSR build (once; reused by both layers) ----
    hist_kernel<<<(E + 255) / 256, 256>>>(dst, deg, E);
    scan1_kernel<<<nb, SCAN_B>>>(deg, lscan, part, N);
    scan2_kernel<<<1, 256>>>(part, nb);
    scan3_kernel<<<(N + 255) / 256, 256>>>(lscan, part, rowptr, cursor, N, E);
    fill_kernel<<<(E + 255) / 256, 256>>>(src, dst, cursor, eidx, E);

    const int gemmBlocks = (N + 63) / 64;

    // ---- Layer 0 aggregation (gather, no atomics) ----
    gather_kernel<16><<<(N + 15) / 16, 256>>>(rowptr, eidx, (const float4*)x,
                                              (float4*)agg0, N);
    // Residual projection: r = x @ Wlin^T + blin
    gemm_kernel<<<gemmBlocks, 256>>>(x, Wlin, nullptr, nullptr, blin, r, nullptr, N, CINn);
    // h0 = x @ Wr0^T + agg0 @ Wn0^T + b0 (+ BN stats)
    gemm_kernel<<<gemmBlocks, 256>>>(x, Wr0, agg0, Wn0, b0, h0, stats, N, CINn);
    finalize_kernel<<<1, 128>>>(stats, g0, be0, bnp, 1.0f / (float)N);
    // y = relu(bn(h0))
    {
        const int T4 = N * 32;
        bnrelu_kernel<<<(T4 + 255) / 256, 256>>>((const float4*)h0, bnp, (float4*)y, T4);
    }
    // ---- Layer 1 aggregation ----
    gather_kernel<32><<<(N + 7) / 8, 256>>>(rowptr, eidx, (const float4*)y,
                                            (float4*)agg1, N);
    // h1 = y @ Wr1^T + agg1 @ Wn1^T + b1 (+ BN stats)
    gemm_kernel<<<gemmBlocks, 256>>>(y, Wr1, agg1, Wn1, b1, h1, stats + 2 * COUTn, N, COUTn);
    finalize_kernel<<<1, 128>>>(stats + 2 * COUTn, g1, be1, bnp + 2 * COUTn, 1.0f / (float)N);
    // out = relu(bn(h1) + r)
    {
        const int T4 = N * 32;
        final_kernel<<<(T4 + 255) / 256, 256>>>((const float4*)h1, bnp + 2 * COUTn,
                                                (const float4*)r, (float4*)out, T4);
    }
}